// round 12
// baseline (speedup 1.0000x reference)
#include <cuda_runtime.h>
#include <cuda_bf16.h>
#include <math.h>

#define NB 128
#define NA 3
#define NC 20
#define NH 52
#define NW 52
#define SPATIAL (NH*NW)      // 2704
#define NT 50
#define NET_SIZE 416.0f
#define NWARPS 16
#define NGRP 8
#define GRPSZ (NB/NGRP)      // 16 blocks per group

__device__ __constant__ float c_aw[NA] = {10.0f, 16.0f, 33.0f};
__device__ __constant__ float c_ah[NA] = {13.0f, 30.0f, 23.0f};

// Scratch (device globals — no allocation allowed)
__device__ double g_gacc[NGRP];     // per-group running sums
__device__ int    g_gticket[NGRP];  // per-group completion tickets
__device__ double g_acc;            // global sum
__device__ int    g_ticket;         // global ticket (counts groups)

// ---------------------------------------------------------------------------
// Single fused kernel. Block b handles batch b; warp w handles target slots
// w, w+16, w+32. Checked value = loss_coord + loss_cls (reference's
// NaN-fallback branch) -> depends only on the scattered winner cells.
// Completion is hierarchical (16-way group stage, 8-way global stage) to
// avoid 128-deep same-address atomic serialization in the tail.
// ---------------------------------------------------------------------------
__global__ __launch_bounds__(NWARPS * 32) void k_all(const float* __restrict__ out,
                                                     const float* __restrict__ tgt,
                                                     float* __restrict__ res) {
    __shared__ float s_tx[NT], s_ty[NT], s_tlw[NT], s_tlh[NT];
    __shared__ int   s_cls[NT];
    __shared__ int   s_base[NT];
    __shared__ int   s_key[NT];
    __shared__ int   s_valid[NT];
    __shared__ float s_wsum[NWARPS];

    int b   = blockIdx.x;
    int tid = threadIdx.x;

    // --- Phase A: parse targets (one thread per target) -------------------
    if (tid < NT) {
        const float* p = tgt + (size_t)b * (5 * NT) + tid * 5;
        float cls = p[0], x = p[1], y = p[2], w = p[3], h = p[4];
        bool v = (x != 0.0f);
        float gx = x * (float)NW;
        float gy = y * (float)NH;
        float gw = w * NET_SIZE;
        float gh = h * NET_SIZE;
        // best anchor: argmax iou((0,0,gw,gh),(0,0,aw,ah)); first max wins
        float best = -1.0f; int bn = 0;
        #pragma unroll
        for (int a = 0; a < NA; a++) {
            float aw = c_aw[a], ah = c_ah[a];
            float inter = fminf(gw, aw) * fminf(gh, ah);
            float uni = gw * gh + aw * ah - inter;
            float iou = inter / fmaxf(uni, 1e-12f);
            if (iou > best) { best = iou; bn = a; }
        }
        int gi = (int)gx;
        int gj = (int)gy;
        // mode='drop' semantics: OOB scatters are dropped
        v = v && (gi >= 0) && (gi < NW) && (gj >= 0) && (gj < NH);

        float aw = c_aw[bn], ah = c_ah[bn];
        s_valid[tid] = v ? 1 : 0;
        s_key[tid]   = (bn * NH + gj) * NW + gi;
        s_tx[tid]  = gx - (float)gi;
        s_ty[tid]  = gy - (float)gj;
        s_tlw[tid] = __logf(fmaxf(gw, 1e-12f) / aw);
        s_tlh[tid] = __logf(fmaxf(gh, 1e-12f) / ah);
        s_cls[tid] = (int)cls;
        s_base[tid] = ((b * 75 + bn * 25) * SPATIAL) + gj * NW + gi;
    }
    __syncthreads();

    // --- Phase B: one warp per target slot; speculative loads overlap the
    //     last-writer-wins dedup scan (smem-only) under the LDG latency. ----
    int wid = tid >> 5, lane = tid & 31;
    float acc = 0.0f;
    #pragma unroll
    for (int t = wid; t < NT; t += NWARPS) {
        if (!s_valid[t]) continue;
        int baseoff = s_base[t];

        // speculative per-lane load + loss value
        float v = 0.0f;
        if (lane < NC) {
            // class BCE-with-logits: max(x,0) - x*onehot + log1p(exp(-|x|))
            float x = out[(size_t)baseoff + (5 + lane) * SPATIAL];
            v = fmaxf(x, 0.0f) + __logf(1.0f + __expf(-fabsf(x)));
            if (lane == s_cls[t]) v -= x;
        } else if (lane == 20) {
            float o  = out[baseoff];
            float sx = 1.0f / (1.0f + __expf(-o));
            float tx = s_tx[t];
            v = -(tx * __logf(fmaxf(sx, 1e-38f)) +
                  (1.0f - tx) * __logf(fmaxf(1.0f - sx, 1e-38f)));
        } else if (lane == 21) {
            float o  = out[(size_t)baseoff + SPATIAL];
            float sy = 1.0f / (1.0f + __expf(-o));
            float ty = s_ty[t];
            v = -(ty * __logf(fmaxf(sy, 1e-38f)) +
                  (1.0f - ty) * __logf(fmaxf(1.0f - sy, 1e-38f)));
        } else if (lane == 22) {
            float o = out[(size_t)baseoff + 2 * SPATIAL];
            float d = o - s_tlw[t];
            v = d * d;
        } else if (lane == 23) {
            float o = out[(size_t)baseoff + 3 * SPATIAL];
            float d = o - s_tlh[t];
            v = d * d;
        }

        // XLA last-writer-wins: t loses if any later valid u has same key.
        // (smem-only; scheduler overlaps this with the loads above)
        bool win = true;
        int key = s_key[t];
        for (int u = t + 1; u < NT; u++)
            if (s_valid[u] && s_key[u] == key) { win = false; break; }

        if (win) acc += v;
    }

    // --- Phase C: block reduce -------------------------------------------
    #pragma unroll
    for (int o = 16; o > 0; o >>= 1)
        acc += __shfl_down_sync(0xffffffff, acc, o);
    if (lane == 0) s_wsum[wid] = acc;
    __syncthreads();

    // --- Phase D: hierarchical completion --------------------------------
    if (tid == 0) {
        float part = 0.0f;
        #pragma unroll
        for (int k = 0; k < NWARPS; k++) part += s_wsum[k];

        int g = b / GRPSZ;
        atomicAdd(&g_gacc[g], (double)part);
        __threadfence();
        if (atomicAdd(&g_gticket[g], 1) == GRPSZ - 1) {
            // group leader: push group sum up
            double gs = atomicAdd(&g_gacc[g], 0.0);
            atomicAdd(&g_acc, gs);
            __threadfence();
            if (atomicAdd(&g_ticket, 1) == NGRP - 1) {
                double s = atomicAdd(&g_acc, 0.0);
                res[0] = (float)(s / (double)NB);
                // reset all state for next graph replay
                #pragma unroll
                for (int k = 0; k < NGRP; k++) { g_gacc[k] = 0.0; g_gticket[k] = 0; }
                g_acc = 0.0;
                g_ticket = 0;
            }
        }
    }
}

extern "C" void kernel_launch(void* const* d_in, const int* in_sizes, int n_in,
                              void* d_out, int out_size) {
    const float* outp = (const float*)d_in[0];   // (128, 75, 52, 52)
    const float* tgt  = (const float*)d_in[1];   // (128, 250)
    float* res = (float*)d_out;

    k_all<<<NB, NWARPS * 32>>>(outp, tgt, res);
}

// round 15
// speedup vs baseline: 1.2384x; 1.2384x over previous
#include <cuda_runtime.h>
#include <cuda_bf16.h>
#include <math.h>

#define NB 128
#define NA 3
#define NC 20
#define NH 52
#define NW 52
#define SPATIAL (NH*NW)      // 2704
#define NT 50
#define NET_SIZE 416.0f
#define NWARPS 16
#define NKEYS (NA*SPATIAL)   // 8112

__device__ __constant__ float c_aw[NA] = {10.0f, 16.0f, 33.0f};
__device__ __constant__ float c_ah[NA] = {13.0f, 30.0f, 23.0f};

// Scratch (device globals — no allocation allowed)
__device__ double g_acc;       // running sum across blocks
__device__ int    g_ticket;    // completion ticket; last block resets

// ---------------------------------------------------------------------------
// Single fused kernel. Block b handles batch b; warp w handles target slots
// w, w+16, w+32. Checked value = loss_coord + loss_cls (reference's
// NaN-fallback branch) -> depends only on the scattered winner cells.
// Dedup (XLA last-writer-wins) is O(1) per target via a shared owner table
// + atomicMax(t) — replaces the serial 49-iteration key scan.
// ---------------------------------------------------------------------------
__global__ __launch_bounds__(NWARPS * 32) void k_all(const float* __restrict__ out,
                                                     const float* __restrict__ tgt,
                                                     float* __restrict__ res) {
    __shared__ int   s_owner[NKEYS];            // max valid t per cell key
    __shared__ float s_tx[NT], s_ty[NT], s_tlw[NT], s_tlh[NT];
    __shared__ int   s_cls[NT];
    __shared__ int   s_base[NT];
    __shared__ int   s_key[NT];
    __shared__ int   s_valid[NT];
    __shared__ float s_wsum[NWARPS];

    int b   = blockIdx.x;
    int tid = threadIdx.x;

    // --- init owner table (vectorized; 8112 ints = 2028 int4) -------------
    {
        int4* p4 = reinterpret_cast<int4*>(s_owner);
        int4 m1 = make_int4(-1, -1, -1, -1);
        for (int k = tid; k < NKEYS / 4; k += NWARPS * 32) p4[k] = m1;
    }
    __syncthreads();

    // --- Phase A: parse targets (one thread per target) + owner scatter ---
    if (tid < NT) {
        const float* p = tgt + (size_t)b * (5 * NT) + tid * 5;
        float cls = p[0], x = p[1], y = p[2], w = p[3], h = p[4];
        bool v = (x != 0.0f);
        float gx = x * (float)NW;
        float gy = y * (float)NH;
        float gw = w * NET_SIZE;
        float gh = h * NET_SIZE;
        // best anchor: argmax iou((0,0,gw,gh),(0,0,aw,ah)); first max wins
        float best = -1.0f; int bn = 0;
        #pragma unroll
        for (int a = 0; a < NA; a++) {
            float aw = c_aw[a], ah = c_ah[a];
            float inter = fminf(gw, aw) * fminf(gh, ah);
            float uni = gw * gh + aw * ah - inter;
            float iou = inter / fmaxf(uni, 1e-12f);
            if (iou > best) { best = iou; bn = a; }
        }
        int gi = (int)gx;
        int gj = (int)gy;
        // mode='drop' semantics: OOB scatters are dropped
        v = v && (gi >= 0) && (gi < NW) && (gj >= 0) && (gj < NH);

        float aw = c_aw[bn], ah = c_ah[bn];
        int key = (bn * NH + gj) * NW + gi;
        s_valid[tid] = v ? 1 : 0;
        s_key[tid]   = key;
        s_tx[tid]  = gx - (float)gi;
        s_ty[tid]  = gy - (float)gj;
        s_tlw[tid] = __logf(fmaxf(gw, 1e-12f) / aw);
        s_tlh[tid] = __logf(fmaxf(gh, 1e-12f) / ah);
        s_cls[tid] = (int)cls;
        s_base[tid] = ((b * 75 + bn * 25) * SPATIAL) + gj * NW + gi;
        if (v) atomicMax(&s_owner[key], tid);   // last-writer-wins == max t
    }
    __syncthreads();

    // --- Phase B: one warp per target slot; O(1) winner check -------------
    int wid = tid >> 5, lane = tid & 31;
    float acc = 0.0f;
    #pragma unroll
    for (int t = wid; t < NT; t += NWARPS) {
        if (!s_valid[t] || s_owner[s_key[t]] != t) continue;   // not the winner
        int baseoff = s_base[t];

        float v = 0.0f;
        if (lane < NC) {
            // class BCE-with-logits: max(x,0) - x*onehot + log1p(exp(-|x|))
            float x = out[(size_t)baseoff + (5 + lane) * SPATIAL];
            v = fmaxf(x, 0.0f) + __logf(1.0f + __expf(-fabsf(x)));
            if (lane == s_cls[t]) v -= x;
        } else if (lane == 20) {
            float o  = out[baseoff];
            float sx = 1.0f / (1.0f + __expf(-o));
            float tx = s_tx[t];
            v = -(tx * __logf(fmaxf(sx, 1e-38f)) +
                  (1.0f - tx) * __logf(fmaxf(1.0f - sx, 1e-38f)));
        } else if (lane == 21) {
            float o  = out[(size_t)baseoff + SPATIAL];
            float sy = 1.0f / (1.0f + __expf(-o));
            float ty = s_ty[t];
            v = -(ty * __logf(fmaxf(sy, 1e-38f)) +
                  (1.0f - ty) * __logf(fmaxf(1.0f - sy, 1e-38f)));
        } else if (lane == 22) {
            float o = out[(size_t)baseoff + 2 * SPATIAL];
            float d = o - s_tlw[t];
            v = d * d;
        } else if (lane == 23) {
            float o = out[(size_t)baseoff + 3 * SPATIAL];
            float d = o - s_tlh[t];
            v = d * d;
        }
        acc += v;
    }

    // --- Phase C: block reduce -------------------------------------------
    #pragma unroll
    for (int o = 16; o > 0; o >>= 1)
        acc += __shfl_down_sync(0xffffffff, acc, o);
    if (lane == 0) s_wsum[wid] = acc;
    __syncthreads();

    // --- Phase D: flat completion (hierarchy measured neutral) ------------
    if (tid == 0) {
        float part = 0.0f;
        #pragma unroll
        for (int k = 0; k < NWARPS; k++) part += s_wsum[k];
        atomicAdd(&g_acc, (double)part);
        __threadfence();
        if (atomicAdd(&g_ticket, 1) == NB - 1) {
            double s = atomicAdd(&g_acc, 0.0);   // L2-coherent read
            res[0] = (float)(s / (double)NB);
            g_acc = 0.0;     // reset for next replay
            g_ticket = 0;
        }
    }
}

extern "C" void kernel_launch(void* const* d_in, const int* in_sizes, int n_in,
                              void* d_out, int out_size) {
    const float* outp = (const float*)d_in[0];   // (128, 75, 52, 52)
    const float* tgt  = (const float*)d_in[1];   // (128, 250)
    float* res = (float*)d_out;

    k_all<<<NB, NWARPS * 32>>>(outp, tgt, res);
}